// round 15
// baseline (speedup 1.0000x reference)
#include <cuda_runtime.h>
#include <math.h>
#include <stdint.h>

#define F      256
#define M      128
#define NMAX   200000
#define NB     128         // nodes per CTA (1 CTA/SM)
#define TPB    256

__device__ float g_H[(size_t)NMAX * M];
__device__ float g_scores[NMAX];
// B images: [q=0..63] each 16KB = bh(8KB) + b'(8KB); rows n:128 x 64B (32 bf16 k), rotation-swizzled
__device__ __align__(128) unsigned char g_Bimg[64 * 16384];
// w1 image: wh 32KB + w' 32KB; rows att:128 x 256B (128 bf16 m), XOR-swizzled
__device__ __align__(128) unsigned char g_W1img[65536];
__device__ float g_cA[1024], g_cB[1024], g_cC[1024];   // gaussian consts
__device__ int g_is64;

// smem layout (1 CTA/SM)
#define SO_XA   0          // A: ah 64KB, a' at +65536 (rows node:128 x 512B swizzled)
#define XA_P    65536
#define SO_STG  131072     // 3 stages x 16384
#define STG_SZ  16384
#define B_P     8192       // b' offset within stage
#define SO_W1   0          // attention phase: w1 hi 32KB, w' +32768
#define SO_HIM  65536      // H image: hh 32KB, h' +32768
#define H_P     32768
#define SO_MB   180224     // mbF[3] @+0, mbE[3] @+24, mbW @+48
#define SMEM_BYTES 180288

__device__ __forceinline__ uint32_t smem_u32(const void* p) {
    uint32_t a;
    asm("{ .reg .u64 t; cvta.to.shared.u64 t, %1; cvt.u32.u64 %0, t; }" : "=r"(a) : "l"(p));
    return a;
}
#define MBAR_INIT(a, c) asm volatile("mbarrier.init.shared.b64 [%0], %1;" :: "r"((uint32_t)(a)), "r"((uint32_t)(c)) : "memory")
#define MBAR_ARRIVE(a)  asm volatile("mbarrier.arrive.shared.b64 _, [%0];" :: "r"((uint32_t)(a)) : "memory")
#define MBAR_EXPECT(a, bytes) \
    asm volatile("mbarrier.arrive.expect_tx.shared.b64 _, [%0], %1;" :: "r"((uint32_t)(a)), "r"((uint32_t)(bytes)) : "memory")
#define MBAR_WAIT(a, par) do { \
    uint32_t _m = (uint32_t)(a), _p = (uint32_t)(par), _d; \
    asm volatile("{\n\t.reg .pred p;\n\t" \
        "mbarrier.try_wait.parity.acquire.cta.shared::cta.b64 p, [%1], %2;\n\t" \
        "selp.b32 %0, 1, 0, p;\n\t}" : "=r"(_d) : "r"(_m), "r"(_p) : "memory"); \
    if (!_d) { asm volatile("{\n\t.reg .pred P1;\n\t" \
        "WL_%=:\n\t" \
        "mbarrier.try_wait.parity.acquire.cta.shared::cta.b64 P1, [%0], %1, 0x989680;\n\t" \
        "@P1 bra.uni WD_%=;\n\tbra.uni WL_%=;\n\tWD_%=:\n\t}" :: "r"(_m), "r"(_p) : "memory"); } \
    } while (0)
#define BULK_G2S(dst, src, bytes, mbar) \
    asm volatile("cp.async.bulk.shared::cta.global.mbarrier::complete_tx::bytes [%0], [%1], %2, [%3];" \
        :: "r"((uint32_t)(dst)), "l"(src), "r"((uint32_t)(bytes)), "r"((uint32_t)(mbar)) : "memory")

__device__ __forceinline__ void ldmx4(uint32_t r[4], uint32_t addr) {
    asm volatile("ldmatrix.sync.aligned.m8n8.x4.shared.b16 {%0,%1,%2,%3}, [%4];"
        : "=r"(r[0]), "=r"(r[1]), "=r"(r[2]), "=r"(r[3]) : "r"(addr));
}
__device__ __forceinline__ void mma_bf16(float* d, const uint32_t* a, uint32_t b0, uint32_t b1) {
    asm volatile("mma.sync.aligned.m16n8k16.row.col.f32.bf16.bf16.f32 "
        "{%0,%1,%2,%3}, {%4,%5,%6,%7}, {%8,%9}, {%0,%1,%2,%3};"
        : "+f"(d[0]), "+f"(d[1]), "+f"(d[2]), "+f"(d[3])
        : "r"(a[0]), "r"(a[1]), "r"(a[2]), "r"(a[3]), "r"(b0), "r"(b1));
}
// 2-term scaled split: ph = bf16x2(a,b); pp = bf16x2(ah+32*(a-ah), bh+32*(b-bh))
__device__ __forceinline__ void split2(float a, float b, uint32_t& ph, uint32_t& pp) {
    asm("cvt.rn.bf16x2.f32 %0, %1, %2;" : "=r"(ph) : "f"(b), "f"(a));
    float ah = __uint_as_float(ph << 16);
    float bh = __uint_as_float(ph & 0xffff0000u);
    float a2 = fmaf(32.f, a - ah, ah);
    float b2 = fmaf(32.f, b - bh, bh);
    asm("cvt.rn.bf16x2.f32 %0, %1, %2;" : "=r"(pp) : "f"(b2), "f"(a2));
}
__device__ __forceinline__ float ex2f(float x) {
    float y; asm("ex2.approx.ftz.f32 %0, %1;" : "=f"(y) : "f"(x)); return y;
}
__device__ __forceinline__ float tanhf_hw(float x) {
    float y; asm("tanh.approx.f32 %0, %1;" : "=f"(y) : "f"(x)); return y;
}

// ---- prep: B images, k32 chunks, rotation swizzle on 64B rows (unchanged layout) ----
__global__ void prep_g(const float* __restrict__ g) {
    int t = blockIdx.x * 256 + threadIdx.x;      // 131072
    int q = t >> 11;                             // chunk 0..63
    int r11 = t & 2047;
    int kp2 = r11 >> 7, nr = r11 & 127;          // k-pair 0..15, n row
    int kb = (q & 7) * 32 + kp2 * 2;             // k within pass
    int nn = (q >> 3) * 128 + nr;
    uint32_t ph, pp;
    split2(g[(size_t)kb * 1024 + nn], g[(size_t)(kb + 1) * 1024 + nn], ph, pp);
    uint32_t off = nr * 64 + ((((uint32_t)(kp2 >> 2) + (uint32_t)(nr >> 1)) & 3) << 4) + (kp2 & 3) * 4;
    unsigned char* base = g_Bimg + (size_t)q * 16384;
    *(uint32_t*)(base + off) = ph;
    *(uint32_t*)(base + B_P + off) = pp;
}
__global__ void prep_w1(const float* __restrict__ w1) {
    int t = blockIdx.x * 256 + threadIdx.x;      // 8192
    int att = t >> 6, mp = t & 63;
    uint32_t ph, pp;
    split2(w1[att * 128 + 2 * mp], w1[att * 128 + 2 * mp + 1], ph, pp);
    uint32_t off = att * 256 + ((((uint32_t)(mp >> 2)) ^ (att & 7)) << 4) + (mp & 3) * 4;
    *(uint32_t*)(g_W1img + off) = ph;
    *(uint32_t*)(g_W1img + 32768 + off) = pp;
}
__global__ void prep_misc(const float* __restrict__ mu, const float* __restrict__ sigma,
                          const int* __restrict__ b32, int n) {
    int i = blockIdx.x * 256 + threadIdx.x;      // 1024
    float s = sigma[i], m_ = mu[i];
    float cc = -0.72134752f / fmaf(s, s, 1e-15f);
    g_cA[i] = cc; g_cB[i] = -2.f * cc * m_; g_cC[i] = cc * m_ * m_;
    if (i == 0) g_is64 = (b32[n - 1] == 0) ? 1 : 0;
}
__device__ __forceinline__ int batch_at(const void* b, int i, int is64) {
    if (is64) return (int)((const long long*)b)[i];
    return ((const int*)b)[i];
}

// half-pass gaussian epilogue: 32 elements (16 rows x 64 cols), then zero
__device__ __forceinline__ void epi_half(float* D1, float* D2, float* H,
                                         const float* pa, const float* pb, const float* pc,
                                         int pofs, int sub)
{
    #pragma unroll
    for (int n8 = 0; n8 < 8; n8++) {
        float2 a2 = *(const float2*)(pa + pofs + n8 * 8);
        float2 b2 = *(const float2*)(pb + pofs + n8 * 8);
        float2 c2 = *(const float2*)(pc + pofs + n8 * 8);
        float* d1 = D1 + sub * 32 + n8 * 4;
        float* d2 = D2 + sub * 32 + n8 * 4;
        float* h  = H  + sub * 32 + n8 * 4;
        float o;
        o = fmaf(d2[0] - d1[0], 0.03125f, d1[0]);
        h[0] = fmaf(o, ex2f(fmaf(fmaf(a2.x, o, b2.x), o, c2.x)), h[0]);
        o = fmaf(d2[1] - d1[1], 0.03125f, d1[1]);
        h[1] = fmaf(o, ex2f(fmaf(fmaf(a2.y, o, b2.y), o, c2.y)), h[1]);
        o = fmaf(d2[2] - d1[2], 0.03125f, d1[2]);
        h[2] = fmaf(o, ex2f(fmaf(fmaf(a2.x, o, b2.x), o, c2.x)), h[2]);
        o = fmaf(d2[3] - d1[3], 0.03125f, d1[3]);
        h[3] = fmaf(o, ex2f(fmaf(fmaf(a2.y, o, b2.y), o, c2.y)), h[3]);
        d1[0] = 0.f; d1[1] = 0.f; d1[2] = 0.f; d1[3] = 0.f;
        d2[0] = 0.f; d2[1] = 0.f; d2[2] = 0.f; d2[3] = 0.f;
    }
}

__global__ __launch_bounds__(TPB, 1)
void node_kernel(const float* __restrict__ x,
                 const float* __restrict__ w2g,
                 float* __restrict__ Hout,
                 float* __restrict__ scores, int n)
{
    extern __shared__ unsigned char smem[];
    const uint32_t sb = smem_u32(smem);
    const uint32_t mbF = sb + SO_MB, mbE = sb + SO_MB + 24, mbW = sb + SO_MB + 48;
    const int tid = threadIdx.x, lane = tid & 31, wid = tid >> 5;
    const int rg = wid >> 1, cg = wid & 1;       // 4 row-groups x 2 col-halves
    const int rsel = lane & 15, usel = lane >> 4;
    const uint32_t xs = (uint32_t)(rsel & 7);
    const int node0 = blockIdx.x * NB;

    if (tid == 0) {
        #pragma unroll
        for (int s2 = 0; s2 < 3; s2++) { MBAR_INIT(mbF + s2 * 8, 1); MBAR_INIT(mbE + s2 * 8, 8); }
        MBAR_INIT(mbW, 1);
    }
    __syncthreads();   // mbar init visible
    if (tid == 0) {    // prefetch chunks 0,1 (overlaps A-image build)
        MBAR_EXPECT(mbF, 16384);
        BULK_G2S(sb + SO_STG, g_Bimg, 16384, mbF);
        MBAR_EXPECT(mbF + 8, 16384);
        BULK_G2S(sb + SO_STG + STG_SZ, g_Bimg + 16384, 16384, mbF + 8);
    }

    // A images: x[128 nodes][256] -> bf16 2-term split, swizzled 512B rows
    #pragma unroll
    for (int j = 0; j < 64; j++) {
        int i = tid + j * TPB;
        int node = i >> 7, kp = i & 127;
        int ng = node0 + node;
        float2 v = make_float2(0.f, 0.f);
        if (ng < n) v = *(const float2*)(x + (size_t)ng * F + kp * 2);
        uint32_t ph, pp; split2(v.x, v.y, ph, pp);
        uint32_t off = node * 512 + ((((uint32_t)(kp >> 2)) ^ (node & 7)) << 4) + (kp & 3) * 4;
        *(uint32_t*)(smem + SO_XA + off) = ph;
        *(uint32_t*)(smem + SO_XA + XA_P + off) = pp;
    }
    __syncthreads();   // A image visible

    float H[64], D1[64], D2[64];
    #pragma unroll
    for (int i = 0; i < 64; i++) { H[i] = 0.f; D1[i] = 0.f; D2[i] = 0.f; }

    const uint32_t aBase0 = sb + SO_XA + (rg * 32 + rsel) * 512;
    const uint32_t aBase1 = aBase0 + 16 * 512;
    uint32_t bRow[4], bSh[4];
    #pragma unroll
    for (int nt = 0; nt < 4; nt++) {
        int rowB = cg * 64 + nt * 16 + rsel;
        bRow[nt] = (uint32_t)(rowB * 64);
        bSh[nt]  = (uint32_t)((rowB >> 1) & 3);
    }
    const float* pa = g_cA + cg * 64 + (lane & 3) * 2;
    const float* pb = g_cB + cg * 64 + (lane & 3) * 2;
    const float* pc = g_cC + cg * 64 + (lane & 3) * 2;

    // incremental parity state (consumer + producer)
    int s = 0, fpar = 0;
    int sq = 2, epar = 0, ecnt = 0;
    #pragma unroll 1
    for (int p8 = 0; p8 < 8; p8++) {
        #pragma unroll
        for (int kc = 0; kc < 8; kc++) {
            const int c = p8 * 8 + kc;
            if (tid == 0) {                    // producer: chunk c+2
                int q = c + 2;
                if (q < 64) {
                    if (q >= 3) MBAR_WAIT(mbE + sq * 8, epar);
                    MBAR_EXPECT(mbF + sq * 8, 16384);
                    BULK_G2S(sb + SO_STG + sq * STG_SZ, g_Bimg + (size_t)q * 16384, 16384, mbF + sq * 8);
                }
            }
            // deferred second-half epilogue of previous pass (overlaps DMA wait)
            if (kc == 0 && p8 > 0)
                epi_half(D1, D2, H, pa, pb, pc, (p8 - 1) * 128, 1);
            MBAR_WAIT(mbF + s * 8, fpar);
            const uint32_t sbase = sb + SO_STG + s * STG_SZ;
            #pragma unroll
            for (int kt = 0; kt < 2; kt++) {
                const uint32_t u = (uint32_t)(kt * 2) + (uint32_t)usel;
                uint32_t offA = ((((uint32_t)(kc * 4) + u) ^ xs) << 4);
                uint32_t af0[4], af1[4], bf[4];
                // hi -> D1
                ldmx4(af0, aBase0 + offA); ldmx4(af1, aBase1 + offA);
                #pragma unroll
                for (int nt = 0; nt < 4; nt++) {
                    uint32_t ba = sbase + bRow[nt] + (((u + bSh[nt]) & 3) << 4);
                    ldmx4(bf, ba);
                    #pragma unroll
                    for (int e = 0; e < 2; e++) {
                        mma_bf16(D1 + (nt * 2 + e) * 4,      af0, bf[e], bf[2 + e]);
                        mma_bf16(D1 + 32 + (nt * 2 + e) * 4, af1, bf[e], bf[2 + e]);
                    }
                }
                // prime -> D2
                ldmx4(af0, aBase0 + offA + XA_P); ldmx4(af1, aBase1 + offA + XA_P);
                #pragma unroll
                for (int nt = 0; nt < 4; nt++) {
                    uint32_t ba = sbase + bRow[nt] + (((u + bSh[nt]) & 3) << 4) + B_P;
                    ldmx4(bf, ba);
                    #pragma unroll
                    for (int e = 0; e < 2; e++) {
                        mma_bf16(D2 + (nt * 2 + e) * 4,      af0, bf[e], bf[2 + e]);
                        mma_bf16(D2 + 32 + (nt * 2 + e) * 4, af1, bf[e], bf[2 + e]);
                    }
                }
            }
            if (lane == 0) MBAR_ARRIVE(mbE + s * 8);   // stage consumed
            if (kc == 7)
                epi_half(D1, D2, H, pa, pb, pc, p8 * 128, 0);
            if (s == 2) { s = 0; fpar ^= 1; } else s++;
            if (tid == 0) {
                if (c + 2 >= 3) { if (++ecnt == 3) { ecnt = 0; epar ^= 1; } }
                sq = (sq == 2) ? 0 : sq + 1;
            }
        }
    }
    __syncthreads();   // all A/stage reads done

    // w1 bulk into XA region; final pass second-half epilogue overlaps it
    if (tid == 0) {
        MBAR_EXPECT(mbW, 65536);
        BULK_G2S(sb + SO_W1, g_W1img, 65536, mbW);
    }
    epi_half(D1, D2, H, pa, pb, pc, 7 * 128, 1);
    {
        #pragma unroll
        for (int sub = 0; sub < 2; sub++) {
            int r0 = node0 + rg * 32 + sub * 16 + (lane >> 2);
            #pragma unroll
            for (int n8 = 0; n8 < 8; n8++) {
                int i = sub * 32 + n8 * 4;
                int m = cg * 64 + n8 * 8 + (lane & 3) * 2;
                if (r0 < n)     *(float2*)(Hout + (size_t)r0 * M + m)       = make_float2(H[i], H[i + 1]);
                if (r0 + 8 < n) *(float2*)(Hout + (size_t)(r0 + 8) * M + m) = make_float2(H[i + 2], H[i + 3]);
            }
        }
        // H image (swizzled 256B rows) at SO_HIM (= old A-prime region)
        #pragma unroll
        for (int sub = 0; sub < 2; sub++) {
            int row0 = rg * 32 + sub * 16 + (lane >> 2);
            uint32_t rx = (uint32_t)(row0 & 7);
            #pragma unroll
            for (int n8 = 0; n8 < 8; n8++) {
                int i = sub * 32 + n8 * 4;
                uint32_t unit = (uint32_t)(cg * 8 + n8);
                uint32_t off = row0 * 256 + ((unit ^ rx) << 4) + (lane & 3) * 4;
                uint32_t ph, pp;
                split2(H[i], H[i + 1], ph, pp);
                *(uint32_t*)(smem + SO_HIM + off) = ph;
                *(uint32_t*)(smem + SO_HIM + H_P + off) = pp;
                split2(H[i + 2], H[i + 3], ph, pp);
                *(uint32_t*)(smem + SO_HIM + off + 8 * 256) = ph;
                *(uint32_t*)(smem + SO_HIM + H_P + off + 8 * 256) = pp;
            }
        }
    }
    MBAR_WAIT(mbW, 0);
    __syncthreads();

    // attention GEMM: warp wid owns rows 16*wid..+15, all 128 att cols (2-term)
    {
        #pragma unroll
        for (int i = 0; i < 64; i++) { D1[i] = 0.f; D2[i] = 0.f; }
        uint32_t hB = sb + SO_HIM + (wid * 16 + rsel) * 256;
        #pragma unroll
        for (int kt = 0; kt < 8; kt++) {
            uint32_t off = ((((uint32_t)(kt * 2 + usel)) ^ xs) << 4);
            uint32_t ah[4], ap[4];
            ldmx4(ah, hB + off); ldmx4(ap, hB + off + H_P);
            #pragma unroll
            for (int nt = 0; nt < 8; nt++) {
                uint32_t bh[4], bp[4];
                uint32_t ba = sb + SO_W1 + (nt * 16 + rsel) * 256 + off;
                ldmx4(bh, ba); ldmx4(bp, ba + 32768);
                #pragma unroll
                for (int e = 0; e < 2; e++) {
                    float* d1 = D1 + (nt * 2 + e) * 4;
                    float* d2 = D2 + (nt * 2 + e) * 4;
                    mma_bf16(d1, ah, bh[e], bh[2 + e]);
                    mma_bf16(d2, ap, bp[e], bp[2 + e]);
                }
            }
        }
        float p0 = 0.f, p1 = 0.f;
        #pragma unroll
        for (int n8 = 0; n8 < 16; n8++) {
            float2 wv = *(const float2*)(w2g + n8 * 8 + (lane & 3) * 2);
            float o;
            o = fmaf(D2[n8*4+0] - D1[n8*4+0], 0.03125f, D1[n8*4+0]);
            p0 = fmaf(tanhf_hw(o), wv.x, p0);
            o = fmaf(D2[n8*4+1] - D1[n8*4+1], 0.03125f, D1[n8*4+1]);
            p0 = fmaf(tanhf_hw(o), wv.y, p0);
            o = fmaf(D2[n8*4+2] - D1[n8*4+2], 0.03125f, D1[n8*4+2]);
            p1 = fmaf(tanhf_hw(o), wv.x, p1);
            o = fmaf(D2[n8*4+3] - D1[n8*4+3], 0.03125f, D1[n8*4+3]);
            p1 = fmaf(tanhf_hw(o), wv.y, p1);
        }
        p0 += __shfl_xor_sync(0xffffffffu, p0, 1);
        p0 += __shfl_xor_sync(0xffffffffu, p0, 2);
        p1 += __shfl_xor_sync(0xffffffffu, p1, 1);
        p1 += __shfl_xor_sync(0xffffffffu, p1, 2);
        if ((lane & 3) == 0) {
            int r = node0 + wid * 16 + (lane >> 2);
            if (r < n) scores[r] = p0;
            if (r + 8 < n) scores[r + 8] = p1;
        }
    }
}

__global__ __launch_bounds__(256)
void pool_kernel(const float* __restrict__ H,
                 const float* __restrict__ scores,
                 const void* __restrict__ batch,
                 int n, float* __restrict__ out)
{
    const int gidx = blockIdx.x, tid = threadIdx.x;
    const int m = tid & 127, half = tid >> 7;
    const int is64 = g_is64;
    int start, end;
    {
        int lo = 0, hi = n;
        while (lo < hi) { int mid = (lo + hi) >> 1; if (batch_at(batch, mid, is64) < gidx) lo = mid + 1; else hi = mid; }
        start = lo; hi = n;
        while (lo < hi) { int mid = (lo + hi) >> 1; if (batch_at(batch, mid, is64) < gidx + 1) lo = mid + 1; else hi = mid; }
        end = lo;
    }
    if (start >= end) { if (half == 0) out[(size_t)gidx * M + m] = 0.f; return; }
    __shared__ float red[256];
    float mx = -INFINITY;
    for (int i = start + tid; i < end; i += 256) mx = fmaxf(mx, scores[i]);
    red[tid] = mx; __syncthreads();
    #pragma unroll
    for (int s = 128; s; s >>= 1) { if (tid < s) red[tid] = fmaxf(red[tid], red[tid + s]); __syncthreads(); }
    mx = red[0]; __syncthreads();
    float sm = 0.f;
    for (int i = start + tid; i < end; i += 256) sm += ex2f(1.442695f * (scores[i] - mx));
    red[tid] = sm; __syncthreads();
    #pragma unroll
    for (int s = 128; s; s >>= 1) { if (tid < s) red[tid] += red[tid + s]; __syncthreads(); }
    const float inv = 1.f / (red[0] + 1e-16f);
    __syncthreads();
    float a0 = 0.f, a1 = 0.f, a2 = 0.f, a3 = 0.f;
    int i = start + half;
    for (; i + 6 < end; i += 8) {
        float w0 = ex2f(1.442695f * (scores[i]     - mx));
        float w1 = ex2f(1.442695f * (scores[i + 2] - mx));
        float w2 = ex2f(1.442695f * (scores[i + 4] - mx));
        float w3 = ex2f(1.442695f * (scores[i + 6] - mx));
        a0 = fmaf(w0, H[(size_t)i * M + m], a0);
        a1 = fmaf(w1, H[(size_t)(i + 2) * M + m], a1);
        a2 = fmaf(w2, H[(size_t)(i + 4) * M + m], a2);
        a3 = fmaf(w3, H[(size_t)(i + 6) * M + m], a3);
    }
    for (; i < end; i += 2)
        a0 = fmaf(ex2f(1.442695f * (scores[i] - mx)), H[(size_t)i * M + m], a0);
    red[tid] = (a0 + a1) + (a2 + a3);
    __syncthreads();
    if (half == 0)
        out[(size_t)gidx * M + m] = (red[m] + red[m + 128]) * inv;
}

extern "C" void kernel_launch(void* const* d_in, const int* in_sizes, int n_in,
                              void* d_out, int out_size)
{
    const float* x     = (const float*)d_in[0];
    const float* g     = (const float*)d_in[1];
    const float* mu    = (const float*)d_in[2];
    const float* sigma = (const float*)d_in[3];
    const float* w1    = (const float*)d_in[4];
    const float* w2    = (const float*)d_in[5];
    const void*  batch = d_in[6];

    int n = in_sizes[0] / F;
    if (n > NMAX) n = NMAX;
    int num_graphs = out_size / M;

    cudaFuncSetAttribute(node_kernel, cudaFuncAttributeMaxDynamicSharedMemorySize, SMEM_BYTES);

    float* Hg; cudaGetSymbolAddress((void**)&Hg, g_H);
    float* Sg; cudaGetSymbolAddress((void**)&Sg, g_scores);

    prep_g<<<512, 256>>>(g);
    prep_w1<<<32, 256>>>(w1);
    prep_misc<<<4, 256>>>(mu, sigma, (const int*)batch, n);
    node_kernel<<<(n + NB - 1) / NB, TPB, SMEM_BYTES>>>(x, w2, Hg, Sg, n);   // 4th launch -> ncu
    pool_kernel<<<num_graphs, 256>>>(Hg, Sg, batch, n, (float*)d_out);
}

// round 16
// speedup vs baseline: 1.0571x; 1.0571x over previous
#include <cuda_runtime.h>
#include <math.h>
#include <stdint.h>

#define F      256
#define M      128
#define NMAX   200000
#define NB     64          // nodes per CTA (2 CTAs/SM)
#define TPB    256

__device__ float g_H[(size_t)NMAX * M];
__device__ float g_scores[NMAX];
// B images: [q=0..63] each 16KB = bh(8KB) + b'(8KB); rows n:128 x 64B (32 bf16 k), rotation-swizzled
__device__ __align__(128) unsigned char g_Bimg[64 * 16384];
// w1 image: wh 32KB + w' 32KB; rows att:128 x 256B (128 bf16 m), XOR-swizzled
__device__ __align__(128) unsigned char g_W1img[65536];
__device__ float g_cA[1024], g_cB[1024], g_cC[1024];   // gaussian consts
__device__ int g_is64;

// smem layout (per CTA, 2 CTAs/SM)
#define SO_XA   0          // A: ah 32KB, a' at +32768 (rows node:64 x 512B swizzled)
#define XA_P    32768
#define SO_STG  65536      // 3 stages x 16384
#define STG_SZ  16384
#define B_P     8192       // b' offset within stage
#define SO_HI   65536      // attention phase: hh 16KB, h' +16384
#define H_P     16384
#define SO_RED  102400     // 64 floats (stage region tail)
#define SO_MB   114688     // mbF[3] @+0, mbE[3] @+24, mbW @+48
#define SMEM_BYTES 114752

__device__ __forceinline__ uint32_t smem_u32(const void* p) {
    uint32_t a;
    asm("{ .reg .u64 t; cvta.to.shared.u64 t, %1; cvt.u32.u64 %0, t; }" : "=r"(a) : "l"(p));
    return a;
}
#define MBAR_INIT(a, c) asm volatile("mbarrier.init.shared.b64 [%0], %1;" :: "r"((uint32_t)(a)), "r"((uint32_t)(c)) : "memory")
#define MBAR_ARRIVE(a)  asm volatile("mbarrier.arrive.shared.b64 _, [%0];" :: "r"((uint32_t)(a)) : "memory")
#define MBAR_EXPECT(a, bytes) \
    asm volatile("mbarrier.arrive.expect_tx.shared.b64 _, [%0], %1;" :: "r"((uint32_t)(a)), "r"((uint32_t)(bytes)) : "memory")
#define MBAR_WAIT(a, par) do { \
    uint32_t _m = (uint32_t)(a), _p = (uint32_t)(par), _d; \
    asm volatile("{\n\t.reg .pred p;\n\t" \
        "mbarrier.try_wait.parity.acquire.cta.shared::cta.b64 p, [%1], %2;\n\t" \
        "selp.b32 %0, 1, 0, p;\n\t}" : "=r"(_d) : "r"(_m), "r"(_p) : "memory"); \
    if (!_d) { asm volatile("{\n\t.reg .pred P1;\n\t" \
        "WL_%=:\n\t" \
        "mbarrier.try_wait.parity.acquire.cta.shared::cta.b64 P1, [%0], %1, 0x989680;\n\t" \
        "@P1 bra.uni WD_%=;\n\tbra.uni WL_%=;\n\tWD_%=:\n\t}" :: "r"(_m), "r"(_p) : "memory"); } \
    } while (0)
#define BULK_G2S(dst, src, bytes, mbar) \
    asm volatile("cp.async.bulk.shared::cta.global.mbarrier::complete_tx::bytes [%0], [%1], %2, [%3];" \
        :: "r"((uint32_t)(dst)), "l"(src), "r"((uint32_t)(bytes)), "r"((uint32_t)(mbar)) : "memory")

__device__ __forceinline__ void ldmx4(uint32_t r[4], uint32_t addr) {
    asm volatile("ldmatrix.sync.aligned.m8n8.x4.shared.b16 {%0,%1,%2,%3}, [%4];"
        : "=r"(r[0]), "=r"(r[1]), "=r"(r[2]), "=r"(r[3]) : "r"(addr));
}
__device__ __forceinline__ void mma_bf16(float* d, const uint32_t* a, uint32_t b0, uint32_t b1) {
    asm volatile("mma.sync.aligned.m16n8k16.row.col.f32.bf16.bf16.f32 "
        "{%0,%1,%2,%3}, {%4,%5,%6,%7}, {%8,%9}, {%0,%1,%2,%3};"
        : "+f"(d[0]), "+f"(d[1]), "+f"(d[2]), "+f"(d[3])
        : "r"(a[0]), "r"(a[1]), "r"(a[2]), "r"(a[3]), "r"(b0), "r"(b1));
}
// 2-term scaled split: ph = bf16x2(a,b); pp = bf16x2(ah+32*(a-ah), bh+32*(b-bh))
__device__ __forceinline__ void split2(float a, float b, uint32_t& ph, uint32_t& pp) {
    asm("cvt.rn.bf16x2.f32 %0, %1, %2;" : "=r"(ph) : "f"(b), "f"(a));
    float ah = __uint_as_float(ph << 16);
    float bh = __uint_as_float(ph & 0xffff0000u);
    float a2 = fmaf(32.f, a - ah, ah);
    float b2 = fmaf(32.f, b - bh, bh);
    asm("cvt.rn.bf16x2.f32 %0, %1, %2;" : "=r"(pp) : "f"(b2), "f"(a2));
}
__device__ __forceinline__ float ex2f(float x) {
    float y; asm("ex2.approx.ftz.f32 %0, %1;" : "=f"(y) : "f"(x)); return y;
}
__device__ __forceinline__ float tanhf_hw(float x) {
    float y; asm("tanh.approx.f32 %0, %1;" : "=f"(y) : "f"(x)); return y;
}

// ---- prep: B images, k32 chunks, rotation swizzle on 64B rows ----
__global__ void prep_g(const float* __restrict__ g) {
    int t = blockIdx.x * 256 + threadIdx.x;      // 131072
    int q = t >> 11;                             // chunk 0..63
    int r11 = t & 2047;
    int kp2 = r11 >> 7, nr = r11 & 127;          // k-pair 0..15, n row
    int kb = (q & 7) * 32 + kp2 * 2;             // k within pass
    int nn = (q >> 3) * 128 + nr;
    uint32_t ph, pp;
    split2(g[(size_t)kb * 1024 + nn], g[(size_t)(kb + 1) * 1024 + nn], ph, pp);
    uint32_t off = nr * 64 + ((((uint32_t)(kp2 >> 2) + (uint32_t)(nr >> 1)) & 3) << 4) + (kp2 & 3) * 4;
    unsigned char* base = g_Bimg + (size_t)q * 16384;
    *(uint32_t*)(base + off) = ph;
    *(uint32_t*)(base + B_P + off) = pp;
}
__global__ void prep_w1(const float* __restrict__ w1) {
    int t = blockIdx.x * 256 + threadIdx.x;      // 8192
    int att = t >> 6, mp = t & 63;
    uint32_t ph, pp;
    split2(w1[att * 128 + 2 * mp], w1[att * 128 + 2 * mp + 1], ph, pp);
    uint32_t off = att * 256 + ((((uint32_t)(mp >> 2)) ^ (att & 7)) << 4) + (mp & 3) * 4;
    *(uint32_t*)(g_W1img + off) = ph;
    *(uint32_t*)(g_W1img + 32768 + off) = pp;
}
__global__ void prep_misc(const float* __restrict__ mu, const float* __restrict__ sigma,
                          const int* __restrict__ b32, int n) {
    int i = blockIdx.x * 256 + threadIdx.x;      // 1024
    float s = sigma[i], m_ = mu[i];
    float cc = -0.72134752f / fmaf(s, s, 1e-15f);
    g_cA[i] = cc; g_cB[i] = -2.f * cc * m_; g_cC[i] = cc * m_ * m_;
    if (i == 0) g_is64 = (b32[n - 1] == 0) ? 1 : 0;
}
__device__ __forceinline__ int batch_at(const void* b, int i, int is64) {
    if (is64) return (int)((const long long*)b)[i];
    return ((const int*)b)[i];
}

// half-pass gaussian epilogue: 16 elements (sub half), then zero
__device__ __forceinline__ void epi_half(float* D1, float* D2, float* H,
                                         const float* pa, const float* pb, const float* pc,
                                         int pofs, int sub)
{
    #pragma unroll
    for (int n8 = 0; n8 < 4; n8++) {
        float2 a2 = *(const float2*)(pa + pofs + n8 * 8);
        float2 b2 = *(const float2*)(pb + pofs + n8 * 8);
        float2 c2 = *(const float2*)(pc + pofs + n8 * 8);
        float* d1 = D1 + sub * 16 + n8 * 4;
        float* d2 = D2 + sub * 16 + n8 * 4;
        float* h  = H  + sub * 16 + n8 * 4;
        float o;
        o = fmaf(d2[0] - d1[0], 0.03125f, d1[0]);
        h[0] = fmaf(o, ex2f(fmaf(fmaf(a2.x, o, b2.x), o, c2.x)), h[0]);
        o = fmaf(d2[1] - d1[1], 0.03125f, d1[1]);
        h[1] = fmaf(o, ex2f(fmaf(fmaf(a2.y, o, b2.y), o, c2.y)), h[1]);
        o = fmaf(d2[2] - d1[2], 0.03125f, d1[2]);
        h[2] = fmaf(o, ex2f(fmaf(fmaf(a2.x, o, b2.x), o, c2.x)), h[2]);
        o = fmaf(d2[3] - d1[3], 0.03125f, d1[3]);
        h[3] = fmaf(o, ex2f(fmaf(fmaf(a2.y, o, b2.y), o, c2.y)), h[3]);
        d1[0] = 0.f; d1[1] = 0.f; d1[2] = 0.f; d1[3] = 0.f;
        d2[0] = 0.f; d2[1] = 0.f; d2[2] = 0.f; d2[3] = 0.f;
    }
}

__global__ __launch_bounds__(TPB, 2)
void node_kernel(const float* __restrict__ x,
                 const float* __restrict__ w2g,
                 float* __restrict__ Hout,
                 float* __restrict__ scores, int n)
{
    extern __shared__ unsigned char smem[];
    const uint32_t sb = smem_u32(smem);
    const uint32_t mbF = sb + SO_MB, mbE = sb + SO_MB + 24, mbW = sb + SO_MB + 48;
    const int tid = threadIdx.x, lane = tid & 31, wid = tid >> 5;
    const int rg = wid >> 2, cg = wid & 3;       // 2 row-groups x 4 col-groups
    const int rsel = lane & 15, usel = lane >> 4;
    const uint32_t xs = (uint32_t)(rsel & 7);
    const int node0 = blockIdx.x * NB;

    if (tid == 0) {
        #pragma unroll
        for (int s2 = 0; s2 < 3; s2++) { MBAR_INIT(mbF + s2 * 8, 1); MBAR_INIT(mbE + s2 * 8, 8); }
        MBAR_INIT(mbW, 1);
    }
    __syncthreads();   // mbar init visible
    if (tid == 0) {    // prefetch chunks 0,1 (overlaps A-image build)
        MBAR_EXPECT(mbF, 16384);
        BULK_G2S(sb + SO_STG, g_Bimg, 16384, mbF);
        MBAR_EXPECT(mbF + 8, 16384);
        BULK_G2S(sb + SO_STG + STG_SZ, g_Bimg + 16384, 16384, mbF + 8);
    }

    // A images: x[64 nodes][256] -> bf16 2-term split, swizzled 512B rows
    #pragma unroll
    for (int j = 0; j < 32; j++) {
        int i = tid + j * TPB;
        int node = i >> 7, kp = i & 127;
        int ng = node0 + node;
        float2 v = make_float2(0.f, 0.f);
        if (ng < n) v = *(const float2*)(x + (size_t)ng * F + kp * 2);
        uint32_t ph, pp; split2(v.x, v.y, ph, pp);
        uint32_t off = node * 512 + ((((uint32_t)(kp >> 2)) ^ (node & 7)) << 4) + (kp & 3) * 4;
        *(uint32_t*)(smem + SO_XA + off) = ph;
        *(uint32_t*)(smem + SO_XA + XA_P + off) = pp;
    }
    __syncthreads();   // A image visible

    float H[32], D1[32], D2[32];
    #pragma unroll
    for (int i = 0; i < 32; i++) { H[i] = 0.f; D1[i] = 0.f; D2[i] = 0.f; }

    const uint32_t aBase0 = sb + SO_XA + (rg * 32 + rsel) * 512;
    const uint32_t aBase1 = aBase0 + 16 * 512;
    uint32_t bRow[2], bSh[2];
    #pragma unroll
    for (int nt = 0; nt < 2; nt++) {
        int rowB = cg * 32 + nt * 16 + rsel;
        bRow[nt] = (uint32_t)(rowB * 64);
        bSh[nt]  = (uint32_t)((rowB >> 1) & 3);
    }
    const float* pa = g_cA + cg * 32 + (lane & 3) * 2;
    const float* pb = g_cB + cg * 32 + (lane & 3) * 2;
    const float* pc = g_cC + cg * 32 + (lane & 3) * 2;

    // incremental parity state (consumer + producer)
    int s = 0, fpar = 0;
    int sq = 2, epar = 0, ecnt = 0;
    #pragma unroll 1
    for (int p8 = 0; p8 < 8; p8++) {
        #pragma unroll
        for (int kc = 0; kc < 8; kc++) {
            const int c = p8 * 8 + kc;
            if (tid == 0) {                    // producer: chunk c+2
                int q = c + 2;
                if (q < 64) {
                    if (q >= 3) MBAR_WAIT(mbE + sq * 8, epar);
                    MBAR_EXPECT(mbF + sq * 8, 16384);
                    BULK_G2S(sb + SO_STG + sq * STG_SZ, g_Bimg + (size_t)q * 16384, 16384, mbF + sq * 8);
                }
            }
            // deferred second-half epilogue of previous pass (overlaps DMA wait)
            if (kc == 0 && p8 > 0)
                epi_half(D1, D2, H, pa, pb, pc, (p8 - 1) * 128, 1);
            // hoisted kt0 A-hi fragments (stage-independent; hides mbF wait)
            uint32_t pf0[4], pf1[4];
            {
                uint32_t offA0 = ((((uint32_t)(kc * 4) + (uint32_t)usel) ^ xs) << 4);
                ldmx4(pf0, aBase0 + offA0);
                ldmx4(pf1, aBase1 + offA0);
            }
            MBAR_WAIT(mbF + s * 8, fpar);
            const uint32_t sbase = sb + SO_STG + s * STG_SZ;
            #pragma unroll
            for (int kt = 0; kt < 2; kt++) {
                const uint32_t u = (uint32_t)(kt * 2) + (uint32_t)usel;
                uint32_t offA = ((((uint32_t)(kc * 4) + u) ^ xs) << 4);
                uint32_t af0[4], af1[4], bf[4];
                // hi -> D1 (kt0 uses preloaded frags)
                if (kt == 0) {
                    #pragma unroll
                    for (int r2 = 0; r2 < 4; r2++) { af0[r2] = pf0[r2]; af1[r2] = pf1[r2]; }
                } else {
                    ldmx4(af0, aBase0 + offA); ldmx4(af1, aBase1 + offA);
                }
                #pragma unroll
                for (int nt = 0; nt < 2; nt++) {
                    uint32_t ba = sbase + bRow[nt] + (((u + bSh[nt]) & 3) << 4);
                    ldmx4(bf, ba);
                    #pragma unroll
                    for (int e = 0; e < 2; e++) {
                        mma_bf16(D1 + (nt * 2 + e) * 4,      af0, bf[e], bf[2 + e]);
                        mma_bf16(D1 + 16 + (nt * 2 + e) * 4, af1, bf[e], bf[2 + e]);
                    }
                }
                // prime -> D2
                ldmx4(af0, aBase0 + offA + XA_P); ldmx4(af1, aBase1 + offA + XA_P);
                #pragma unroll
                for (int nt = 0; nt < 2; nt++) {
                    uint32_t ba = sbase + bRow[nt] + (((u + bSh[nt]) & 3) << 4) + B_P;
                    ldmx4(bf, ba);
                    #pragma unroll
                    for (int e = 0; e < 2; e++) {
                        mma_bf16(D2 + (nt * 2 + e) * 4,      af0, bf[e], bf[2 + e]);
                        mma_bf16(D2 + 16 + (nt * 2 + e) * 4, af1, bf[e], bf[2 + e]);
                    }
                }
            }
            if (lane == 0) MBAR_ARRIVE(mbE + s * 8);   // stage consumed
            if (kc == 7)
                epi_half(D1, D2, H, pa, pb, pc, p8 * 128, 0);
            if (s == 2) { s = 0; fpar ^= 1; } else s++;
            if (tid == 0) {
                if (c + 2 >= 3) { if (++ecnt == 3) { ecnt = 0; epar ^= 1; } }
                sq = (sq == 2) ? 0 : sq + 1;
            }
        }
    }
    __syncthreads();   // all A/stage reads done

    // w1 bulk into A region; final pass second-half epilogue overlaps it
    if (tid == 0) {
        MBAR_EXPECT(mbW, 65536);
        BULK_G2S(sb + SO_XA, g_W1img, 65536, mbW);
    }
    epi_half(D1, D2, H, pa, pb, pc, 7 * 128, 1);
    {
        #pragma unroll
        for (int sub = 0; sub < 2; sub++) {
            int r0 = node0 + rg * 32 + sub * 16 + (lane >> 2);
            #pragma unroll
            for (int n8 = 0; n8 < 4; n8++) {
                int i = sub * 16 + n8 * 4;
                int m = cg * 32 + n8 * 8 + (lane & 3) * 2;
                if (r0 < n)     *(float2*)(Hout + (size_t)r0 * M + m)       = make_float2(H[i], H[i + 1]);
                if (r0 + 8 < n) *(float2*)(Hout + (size_t)(r0 + 8) * M + m) = make_float2(H[i + 2], H[i + 3]);
            }
        }
        #pragma unroll
        for (int sub = 0; sub < 2; sub++) {
            int row0 = rg * 32 + sub * 16 + (lane >> 2);
            uint32_t rx = (uint32_t)(row0 & 7);
            #pragma unroll
            for (int n8 = 0; n8 < 4; n8++) {
                int i = sub * 16 + n8 * 4;
                uint32_t unit = (uint32_t)(cg * 4 + n8);
                uint32_t off = row0 * 256 + ((unit ^ rx) << 4) + (lane & 3) * 4;
                uint32_t ph, pp;
                split2(H[i], H[i + 1], ph, pp);
                *(uint32_t*)(smem + SO_HI + off) = ph;
                *(uint32_t*)(smem + SO_HI + H_P + off) = pp;
                split2(H[i + 2], H[i + 3], ph, pp);
                *(uint32_t*)(smem + SO_HI + off + 8 * 256) = ph;
                *(uint32_t*)(smem + SO_HI + H_P + off + 8 * 256) = pp;
            }
        }
    }
    MBAR_WAIT(mbW, 0);
    __syncthreads();

    // attention GEMM: warp = (row-16-group rw 0..3, att-col-half cq)
    {
        const int rw = wid >> 1, cq = wid & 1;
        float* sred = (float*)(smem + SO_RED);
        #pragma unroll
        for (int i = 0; i < 32; i++) { D1[i] = 0.f; D2[i] = 0.f; }
        uint32_t hB = sb + SO_HI + (rw * 16 + rsel) * 256;
        #pragma unroll
        for (int kt = 0; kt < 8; kt++) {
            uint32_t off = ((((uint32_t)(kt * 2 + usel)) ^ xs) << 4);
            uint32_t ah[4], ap[4];
            ldmx4(ah, hB + off); ldmx4(ap, hB + off + H_P);
            #pragma unroll
            for (int nt = 0; nt < 4; nt++) {
                uint32_t bh[4], bp[4];
                uint32_t ba = sb + SO_XA + (cq * 64 + nt * 16 + rsel) * 256 + off;
                ldmx4(bh, ba); ldmx4(bp, ba + 32768);
                #pragma unroll
                for (int e = 0; e < 2; e++) {
                    float* d1 = D1 + (nt * 2 + e) * 4;
                    float* d2 = D2 + (nt * 2 + e) * 4;
                    mma_bf16(d1, ah, bh[e], bh[2 + e]);
                    mma_bf16(d2, ap, bp[e], bp[2 + e]);
                }
            }
        }
        float p0 = 0.f, p1 = 0.f;
        #pragma unroll
        for (int n8 = 0; n8 < 8; n8++) {
            float2 wv = *(const float2*)(w2g + cq * 64 + n8 * 8 + (lane & 3) * 2);
            float o;
            o = fmaf(D2[n8*4+0] - D1[n8*4+0], 0.03125f, D1[n8*4+0]);
            p0 = fmaf(tanhf_hw(o), wv.x, p0);
            o = fmaf(D2[n8*4+1] - D1[n8*4+1], 0.03125f, D1[n8*4+1]);
            p0 = fmaf(tanhf_hw(o), wv.y, p0);
            o = fmaf(D2[n8*4+2] - D1[n8*4+2], 0.03125f, D1[n8*4+2]);
            p1 = fmaf(tanhf_hw(o), wv.x, p1);
            o = fmaf(D2[n8*4+3] - D1[n8*4+3], 0.03125f, D1[n8*4+3]);
            p1 = fmaf(tanhf_hw(o), wv.y, p1);
        }
        p0 += __shfl_xor_sync(0xffffffffu, p0, 1);
        p0 += __shfl_xor_sync(0xffffffffu, p0, 2);
        p1 += __shfl_xor_sync(0xffffffffu, p1, 1);
        p1 += __shfl_xor_sync(0xffffffffu, p1, 2);
        if (cq == 1 && (lane & 3) == 0) {
            sred[rw * 16 + (lane >> 2)] = p0;
            sred[rw * 16 + 8 + (lane >> 2)] = p1;
        }
        __syncthreads();
        if (cq == 0 && (lane & 3) == 0) {
            int r = node0 + rw * 16 + (lane >> 2);
            if (r < n) scores[r] = p0 + sred[rw * 16 + (lane >> 2)];
            if (r + 8 < n) scores[r + 8] = p1 + sred[rw * 16 + 8 + (lane >> 2)];
        }
    }
}

__global__ __launch_bounds__(256)
void pool_kernel(const float* __restrict__ H,
                 const float* __restrict__ scores,
                 const void* __restrict__ batch,
                 int n, float* __restrict__ out)
{
    const int gidx = blockIdx.x, tid = threadIdx.x;
    const int m = tid & 127, half = tid >> 7;
    const int is64 = g_is64;
    int start, end;
    {
        int lo = 0, hi = n;
        while (lo < hi) { int mid = (lo + hi) >> 1; if (batch_at(batch, mid, is64) < gidx) lo = mid + 1; else hi = mid; }
        start = lo; hi = n;
        while (lo < hi) { int mid = (lo + hi) >> 1; if (batch_at(batch, mid, is64) < gidx + 1) lo = mid + 1; else hi = mid; }
        end = lo;
    }
    if (start >= end) { if (half == 0) out[(size_t)gidx * M + m] = 0.f; return; }
    __shared__ float red[256];
    float mx = -INFINITY;
    for (int i = start + tid; i < end; i += 256) mx = fmaxf(mx, scores[i]);
    red[tid] = mx; __syncthreads();
    #pragma unroll
    for (int s = 128; s; s >>= 1) { if (tid < s) red[tid] = fmaxf(red[tid], red[tid + s]); __syncthreads(); }
    mx = red[0]; __syncthreads();
    float sm = 0.f;
    for (int i = start + tid; i < end; i += 256) sm += ex2f(1.442695f * (scores[i] - mx));
    red[tid] = sm; __syncthreads();
    #pragma unroll
    for (int s = 128; s; s >>= 1) { if (tid < s) red[tid] += red[tid + s]; __syncthreads(); }
    const float inv = 1.f / (red[0] + 1e-16f);
    __syncthreads();
    float a0 = 0.f, a1 = 0.f, a2 = 0.f, a3 = 0.f;
    int i = start + half;
    for (; i + 6 < end; i += 8) {
        float w0 = ex2f(1.442695f * (scores[i]     - mx));
        float w1 = ex2f(1.442695f * (scores[i + 2] - mx));
        float w2 = ex2f(1.442695f * (scores[i + 4] - mx));
        float w3 = ex2f(1.442695f * (scores[i + 6] - mx));
        a0 = fmaf(w0, H[(size_t)i * M + m], a0);
        a1 = fmaf(w1, H[(size_t)(i + 2) * M + m], a1);
        a2 = fmaf(w2, H[(size_t)(i + 4) * M + m], a2);
        a3 = fmaf(w3, H[(size_t)(i + 6) * M + m], a3);
    }
    for (; i < end; i += 2)
        a0 = fmaf(ex2f(1.442695f * (scores[i] - mx)), H[(size_t)i * M + m], a0);
    red[tid] = (a0 + a1) + (a2 + a3);
    __syncthreads();
    if (half == 0)
        out[(size_t)gidx * M + m] = (red[m] + red[m + 128]) * inv;
}

extern "C" void kernel_launch(void* const* d_in, const int* in_sizes, int n_in,
                              void* d_out, int out_size)
{
    const float* x     = (const float*)d_in[0];
    const float* g     = (const float*)d_in[1];
    const float* mu    = (const float*)d_in[2];
    const float* sigma = (const float*)d_in[3];
    const float* w1    = (const float*)d_in[4];
    const float* w2    = (const float*)d_in[5];
    const void*  batch = d_in[6];

    int n = in_sizes[0] / F;
    if (n > NMAX) n = NMAX;
    int num_graphs = out_size / M;

    cudaFuncSetAttribute(node_kernel, cudaFuncAttributeMaxDynamicSharedMemorySize, SMEM_BYTES);

    float* Hg; cudaGetSymbolAddress((void**)&Hg, g_H);
    float* Sg; cudaGetSymbolAddress((void**)&Sg, g_scores);

    prep_g<<<512, 256>>>(g);
    prep_w1<<<32, 256>>>(w1);
    prep_misc<<<4, 256>>>(mu, sigma, (const int*)batch, n);
    node_kernel<<<(n + NB - 1) / NB, TPB, SMEM_BYTES>>>(x, w2, Hg, Sg, n);   // 4th launch -> ncu
    pool_kernel<<<num_graphs, 256>>>(Hg, Sg, batch, n, (float*)d_out);
}